// round 2
// baseline (speedup 1.0000x reference)
#include <cuda_runtime.h>
#include <math.h>

#define GSZ 32
#define LL  1024
#define BB  4
#define NNB 20
#define CC  128
#define HH  8
#define WW  32
#define HW  256
#define NRAY 360

// ---------------- scratch (device globals; no allocations) ----------------
__device__ float g_R[NRAY*HW];
__device__ float g_eR[NRAY*HW];
__device__ float g_P[BB*NNB*HW];
__device__ float g_eP[BB*NNB*HW];
__device__ float g_pano[BB*NNB*2*HW];
__device__ float g_T[BB*NNB*NRAY];
__device__ float g_G[(size_t)BB*NNB*NRAY*CC];   // 14.7 MB
__device__ int   g_ind[BB*LL*NNB];
__device__ float g_eD[BB*LL*NNB];
__device__ float g_invZ[BB*LL];
__device__ float g_alpha;
__device__ float g_Rmax;
__device__ float g_Pmax;

__device__ inline void atomicMaxF(float* addr, float val) {
    if (val >= 0.f) atomicMax((int*)addr, __float_as_int(val));
    else            atomicMin((unsigned int*)addr, __float_as_uint(val));
}

// ---------------- setup: alpha + reset maxes (idempotent per launch) ------
__global__ void k_setup(const float* __restrict__ w1, const float* __restrict__ w2,
                        const float* __restrict__ fw) {
    float s1 = 0.f, s2 = 0.f;
    for (int i = 0; i < 9; i++)  s1 += w1[i];   // conv1 distance channel taps
    for (int i = 0; i < 25; i++) s2 += w2[i];   // conv2 distance channel taps
    g_alpha = fw[0]*s1 + fw[1]*s2;
    g_Rmax = -1e30f;
    g_Pmax = -1e30f;
}

// ---------------- pano: per-(b,p,h,w) max/mean over C ---------------------
__global__ void k_pano(const float* __restrict__ feats) {
    int bp = blockIdx.x;
    int t  = threadIdx.x;
    const float* base = feats + (size_t)bp*CC*HW + t;
    float mx = -3.4e38f, sm = 0.f;
    for (int c = 0; c < CC; c++) {
        float v = base[(size_t)c*HW];
        mx = fmaxf(mx, v);
        sm += v;
    }
    g_pano[bp*2*HW + t]      = mx;
    g_pano[bp*2*HW + HW + t] = sm * (1.0f/128.0f);
}

// ---------------- R table: combined circular conv of each ray -------------
__global__ void k_R(const float* __restrict__ rays, const float* __restrict__ w1,
                    const float* __restrict__ w2, const float* __restrict__ fw) {
    int ind = blockIdx.x, t = threadIdx.x;
    __shared__ float sr[3*HW];
    __shared__ float sw1[27], sw2[75];
    __shared__ float red[256];
    for (int i = t; i < 3*HW; i += 256) sr[i] = rays[(size_t)ind*3*HW + i];
    if (t < 27) sw1[t] = w1[9  + t];   // channels 1..3 of conv1
    if (t < 75) sw2[t] = w2[25 + t];   // channels 1..3 of conv2
    __syncthreads();
    int y = t >> 5, x = t & 31;
    float a1 = 0.f, a2 = 0.f;
    #pragma unroll
    for (int c = 0; c < 3; c++) {
        const float* rc = sr + c*HW;
        #pragma unroll
        for (int ky = 0; ky < 3; ky++) {
            int yy = ((y + ky + 7) & 7) * 32;
            #pragma unroll
            for (int kx = 0; kx < 3; kx++)
                a1 = fmaf(sw1[c*9 + ky*3 + kx], rc[yy + ((x + kx + 31) & 31)], a1);
        }
        #pragma unroll
        for (int ky = 0; ky < 5; ky++) {
            int yy = ((y + ky + 6) & 7) * 32;
            #pragma unroll
            for (int kx = 0; kx < 5; kx++)
                a2 = fmaf(sw2[c*25 + ky*5 + kx], rc[yy + ((x + kx + 30) & 31)], a2);
        }
    }
    float R = fw[0]*a1 + fw[1]*a2;
    g_R[ind*HW + t] = R;
    red[t] = R; __syncthreads();
    for (int off = 128; off > 0; off >>= 1) {
        if (t < off) red[t] = fmaxf(red[t], red[t+off]);
        __syncthreads();
    }
    if (t == 0) atomicMaxF(&g_Rmax, red[0]);
}

// ---------------- P table: combined circular conv of pano channels --------
__global__ void k_P(const float* __restrict__ w1, const float* __restrict__ w2,
                    const float* __restrict__ fw) {
    int bp = blockIdx.x, t = threadIdx.x;
    __shared__ float sp[2*HW];
    __shared__ float sw1[18], sw2[50];
    __shared__ float red[256];
    for (int i = t; i < 2*HW; i += 256) sp[i] = g_pano[bp*2*HW + i];
    if (t < 18) sw1[t] = w1[4*9  + t];  // channels 4..5 of conv1
    if (t < 50) sw2[t] = w2[4*25 + t];  // channels 4..5 of conv2
    __syncthreads();
    int y = t >> 5, x = t & 31;
    float a1 = 0.f, a2 = 0.f;
    #pragma unroll
    for (int m = 0; m < 2; m++) {
        const float* pc = sp + m*HW;
        #pragma unroll
        for (int ky = 0; ky < 3; ky++) {
            int yy = ((y + ky + 7) & 7) * 32;
            #pragma unroll
            for (int kx = 0; kx < 3; kx++)
                a1 = fmaf(sw1[m*9 + ky*3 + kx], pc[yy + ((x + kx + 31) & 31)], a1);
        }
        #pragma unroll
        for (int ky = 0; ky < 5; ky++) {
            int yy = ((y + ky + 6) & 7) * 32;
            #pragma unroll
            for (int kx = 0; kx < 5; kx++)
                a2 = fmaf(sw2[m*25 + ky*5 + kx], pc[yy + ((x + kx + 30) & 31)], a2);
        }
    }
    float P = fw[0]*a1 + fw[1]*a2;
    g_P[bp*HW + t] = P;
    red[t] = P; __syncthreads();
    for (int off = 128; off > 0; off >>= 1) {
        if (t < off) red[t] = fmaxf(red[t], red[t+off]);
        __syncthreads();
    }
    if (t == 0) atomicMaxF(&g_Pmax, red[0]);
}

// ---------------- exp of shifted tables ------------------------------------
__global__ void k_exp() {
    int i = blockIdx.x * blockDim.x + threadIdx.x;
    if (i < NRAY*HW) g_eR[i] = expf(g_R[i] - g_Rmax);
    int j = i - NRAY*HW;
    if (j >= 0 && j < BB*NNB*HW) g_eP[j] = expf(g_P[j] - g_Pmax);
}

// ---------------- T[bp,ind] = sum_hw eP*eR ---------------------------------
__global__ void k_T() {
    int blk = blockIdx.x;              // bp*360 + ind
    int bp = blk / NRAY, ind = blk % NRAY;
    int t = threadIdx.x;
    __shared__ float red[256];
    red[t] = g_eP[bp*HW + t] * g_eR[ind*HW + t];
    __syncthreads();
    for (int off = 128; off > 0; off >>= 1) {
        if (t < off) red[t] += red[t+off];
        __syncthreads();
    }
    if (t == 0) g_T[blk] = red[0];
}

// ---------------- geometry: ind, eD, Z per (b,s,p) --------------------------
__global__ void k_geo(const float* __restrict__ bbox, const float* __restrict__ locs) {
    int b = blockIdx.x;
    int s = threadIdx.x;
    __shared__ float sT[NNB*NRAY];
    __shared__ float sl[NNB*2];
    __shared__ float sb[4];
    for (int i = s; i < NNB*NRAY; i += 1024) sT[i] = g_T[b*NNB*NRAY + i];
    if (s < NNB*2) sl[s] = locs[b*NNB*2 + s];
    if (s < 4)     sb[s] = bbox[b*4 + s];
    __syncthreads();
    int iy = s >> 5, ix = s & 31;
    // linspace in f32, mirroring jnp: start + i*((stop-start)/(n-1))
    float ystep = __fdiv_rn(sb[2] - sb[0], 31.0f);
    float xstep = __fdiv_rn(sb[3] - sb[1], 31.0f);
    float py = __fadd_rn(sb[0], __fmul_rn((float)iy, ystep));
    float px = __fadd_rn(sb[1], __fmul_rn((float)ix, xstep));
    float alpha = g_alpha;
    float Z = 0.f;
    int base = (b*LL + s)*NNB;
    for (int p = 0; p < NNB; p++) {
        float dy = py - sl[2*p];
        float dx = px - sl[2*p + 1];
        float D = sqrtf(__fadd_rn(__fadd_rn(__fmul_rn(dy,dy), __fmul_rn(dx,dx)), 1e-12f));
        float th = atan2f(dx, dy);
        if (th < 0.f) th += 6.283185307179586f;
        float deg = __fmul_rn(th, 57.29577951308232f);
        int ind = (int)rintf(deg);          // round half-even, matches jnp.round
        if (ind >= 360) ind -= 360;
        float eD = expf(alpha * D);
        g_ind[base + p] = ind;
        g_eD[base + p]  = eD;
        Z = fmaf(eD, sT[p*NRAY + ind], Z);
    }
    g_invZ[b*LL + s] = 1.0f / Z;
}

// ---------------- G GEMM: per (b,p)  G[ind,f] = sum_hw eR[ind,hw]*feats[f,hw]*eP[hw]
#define TM 64
#define TN 128
#define TK 16
__global__ void k_gemmG(const float* __restrict__ feats) {
    int m0 = blockIdx.x * TM;                  // ind tile
    int bp = blockIdx.z * NNB + blockIdx.y;    // (b,p)
    const float* fbase = feats + (size_t)bp*CC*HW;
    const float* epb   = g_eP + bp*HW;
    __shared__ float As[TK][TM];               // [k][ind]
    __shared__ float Bs[TK][TN];               // [k][f]
    int tid = threadIdx.x;
    int tx = tid & 15;      // f group (8 wide)
    int ty = tid >> 4;      // ind group (4 wide)
    float acc[4][8];
    #pragma unroll
    for (int i = 0; i < 4; i++)
        #pragma unroll
        for (int j = 0; j < 8; j++) acc[i][j] = 0.f;

    int a_mi = tid >> 2, a_kq = tid & 3;   // A: 64 m x (4 floats of k) each
    int b_fi = tid >> 1, b_kq = tid & 1;   // B: 128 f x (8 floats of k) each

    for (int k0 = 0; k0 < HW; k0 += TK) {
        float4 av = make_float4(0.f,0.f,0.f,0.f);
        int m = m0 + a_mi;
        if (m < NRAY) av = *(const float4*)(g_eR + (size_t)m*HW + k0 + a_kq*4);
        As[a_kq*4+0][a_mi] = av.x;
        As[a_kq*4+1][a_mi] = av.y;
        As[a_kq*4+2][a_mi] = av.z;
        As[a_kq*4+3][a_mi] = av.w;
        #pragma unroll
        for (int q = 0; q < 2; q++) {
            int kk = b_kq*8 + q*4;
            float4 fv = *(const float4*)(fbase + (size_t)b_fi*HW + k0 + kk);
            float4 ev = *(const float4*)(epb + k0 + kk);
            Bs[kk+0][b_fi] = fv.x*ev.x;
            Bs[kk+1][b_fi] = fv.y*ev.y;
            Bs[kk+2][b_fi] = fv.z*ev.z;
            Bs[kk+3][b_fi] = fv.w*ev.w;
        }
        __syncthreads();
        #pragma unroll
        for (int kk = 0; kk < TK; kk++) {
            float a[4], bb[8];
            #pragma unroll
            for (int i = 0; i < 4; i++) a[i]  = As[kk][ty*4 + i];
            #pragma unroll
            for (int j = 0; j < 8; j++) bb[j] = Bs[kk][tx*8 + j];
            #pragma unroll
            for (int i = 0; i < 4; i++)
                #pragma unroll
                for (int j = 0; j < 8; j++) acc[i][j] = fmaf(a[i], bb[j], acc[i][j]);
        }
        __syncthreads();
    }
    float* gb = g_G + ((size_t)bp*NRAY + m0)*CC;
    #pragma unroll
    for (int i = 0; i < 4; i++) {
        int m = ty*4 + i;
        if (m0 + m < NRAY) {
            #pragma unroll
            for (int j = 0; j < 8; j++)
                gb[(size_t)m*CC + tx*8 + j] = acc[i][j];
        }
    }
}

// ---------------- grid_feats output ----------------------------------------
__global__ void k_out(float* __restrict__ out) {
    int b = blockIdx.y, s = blockIdx.x, t = threadIdx.x;
    __shared__ int   si[NNB];
    __shared__ float se[NNB];
    int base = (b*LL + s)*NNB;
    if (t < NNB) { si[t] = g_ind[base + t]; se[t] = g_eD[base + t]; }
    __syncthreads();
    float acc = 0.f;
    #pragma unroll
    for (int p = 0; p < NNB; p++) {
        const float* g = g_G + ((size_t)(b*NNB + p)*NRAY + si[p])*CC;
        acc = fmaf(se[p], g[t], acc);
    }
    out[(size_t)(b*LL + s)*CC + t] = acc * g_invZ[b*LL + s];
}

// ---------------- attn output ----------------------------------------------
__global__ void k_attn(float* __restrict__ out) {
    int p = blockIdx.x, s = blockIdx.y, b = blockIdx.z, t = threadIdx.x;
    int idx = (b*LL + s)*NNB + p;
    float sc = g_eD[idx] * g_invZ[b*LL + s];
    int ind = g_ind[idx];
    float v = sc * g_eP[(b*NNB + p)*HW + t] * g_eR[ind*HW + t];
    out[(size_t)BB*LL*CC + (size_t)idx*HW + t] = v;
}

// ---------------- launch -----------------------------------------------------
extern "C" void kernel_launch(void* const* d_in, const int* in_sizes, int n_in,
                              void* d_out, int out_size) {
    const float* bbox  = (const float*)d_in[0];
    const float* locs  = (const float*)d_in[1];
    const float* feats = (const float*)d_in[2];
    // d_in[3] = overhead_feat: cancels in the softmax -> unused
    const float* rays  = (const float*)d_in[4];
    const float* w1    = (const float*)d_in[5];
    const float* w2    = (const float*)d_in[7];
    const float* fw    = (const float*)d_in[9];
    float* out = (float*)d_out;

    k_setup<<<1, 1>>>(w1, w2, fw);
    k_pano<<<BB*NNB, 256>>>(feats);
    k_R<<<NRAY, 256>>>(rays, w1, w2, fw);
    k_P<<<BB*NNB, 256>>>(w1, w2, fw);
    k_exp<<<(NRAY*HW + BB*NNB*HW + 255)/256, 256>>>();
    k_T<<<BB*NNB*NRAY, 256>>>();
    k_geo<<<BB, 1024>>>(bbox, locs);
    dim3 gg(6, NNB, BB);
    k_gemmG<<<gg, 256>>>(feats);
    dim3 go(LL, BB);
    k_out<<<go, 128>>>(out);
    dim3 ga(NNB, LL, BB);
    k_attn<<<ga, 256>>>(out);
}

// round 3
// speedup vs baseline: 1.3084x; 1.3084x over previous
#include <cuda_runtime.h>
#include <math.h>

#define GSZ 32
#define LL  1024
#define BB  4
#define NNB 20
#define CC  128
#define HH  8
#define WW  32
#define HW  256
#define NRAY 360

// packed f32x2 FMA (Blackwell): one inst = 2 fp32 FMAs
#define FMA_F32X2(d,a,b,c) asm("fma.rn.f32x2 %0, %1, %2, %3;" : "=l"(d) : "l"(a), "l"(b), "l"(c))

// ---------------- scratch (device globals; no allocations) ----------------
__device__ float g_R[NRAY*HW];
__device__ float g_eR[NRAY*HW];
__device__ float g_P[BB*NNB*HW];
__device__ float g_eP[BB*NNB*HW];
__device__ float g_pano[BB*NNB*2*HW];
__device__ float g_T[BB*NNB*NRAY];
__device__ float g_G[(size_t)BB*NNB*NRAY*CC];   // 14.7 MB
__device__ int   g_ind[BB*LL*NNB];
__device__ float g_eD[BB*LL*NNB];
__device__ float g_invZ[BB*LL];
__device__ float g_alpha;
__device__ float g_Rmax;
__device__ float g_Pmax;

__device__ inline void atomicMaxF(float* addr, float val) {
    if (val >= 0.f) atomicMax((int*)addr, __float_as_int(val));
    else            atomicMin((unsigned int*)addr, __float_as_uint(val));
}

// ---------------- pano (+ folded setup): per-(b,p,h,w) max/mean over C ----
__global__ void k_pano(const float* __restrict__ feats,
                       const float* __restrict__ w1, const float* __restrict__ w2,
                       const float* __restrict__ fw) {
    if (blockIdx.x == 0 && threadIdx.x == 0) {
        float s1 = 0.f, s2 = 0.f;
        for (int i = 0; i < 9; i++)  s1 += w1[i];
        for (int i = 0; i < 25; i++) s2 += w2[i];
        g_alpha = fw[0]*s1 + fw[1]*s2;
        g_Rmax = -1e30f;
        g_Pmax = -1e30f;
    }
    int bp = blockIdx.x;
    int t  = threadIdx.x;
    const float* base = feats + (size_t)bp*CC*HW + t;
    float mx = -3.4e38f, sm = 0.f;
    #pragma unroll 8
    for (int c = 0; c < CC; c++) {
        float v = base[(size_t)c*HW];
        mx = fmaxf(mx, v);
        sm += v;
    }
    g_pano[bp*2*HW + t]      = mx;
    g_pano[bp*2*HW + HW + t] = sm * (1.0f/128.0f);
}

// ---------------- merged R + P tables (combined circular convs) -----------
__global__ void k_RP(const float* __restrict__ rays, const float* __restrict__ w1,
                     const float* __restrict__ w2, const float* __restrict__ fw) {
    __shared__ float sbuf[3*HW];
    __shared__ float sw1[27], sw2[75];
    __shared__ float red[256];
    int t = threadIdx.x;
    int y = t >> 5, x = t & 31;

    if (blockIdx.x < NRAY) {
        int ind = blockIdx.x;
        for (int i = t; i < 3*HW; i += 256) sbuf[i] = rays[(size_t)ind*3*HW + i];
        if (t < 27) sw1[t] = w1[9  + t];
        if (t < 75) sw2[t] = w2[25 + t];
        __syncthreads();
        float a1 = 0.f, a2 = 0.f;
        #pragma unroll
        for (int c = 0; c < 3; c++) {
            const float* rc = sbuf + c*HW;
            #pragma unroll
            for (int ky = 0; ky < 3; ky++) {
                int yy = ((y + ky + 7) & 7) * 32;
                #pragma unroll
                for (int kx = 0; kx < 3; kx++)
                    a1 = fmaf(sw1[c*9 + ky*3 + kx], rc[yy + ((x + kx + 31) & 31)], a1);
            }
            #pragma unroll
            for (int ky = 0; ky < 5; ky++) {
                int yy = ((y + ky + 6) & 7) * 32;
                #pragma unroll
                for (int kx = 0; kx < 5; kx++)
                    a2 = fmaf(sw2[c*25 + ky*5 + kx], rc[yy + ((x + kx + 30) & 31)], a2);
            }
        }
        float R = fw[0]*a1 + fw[1]*a2;
        g_R[ind*HW + t] = R;
        red[t] = R; __syncthreads();
        for (int off = 128; off > 0; off >>= 1) {
            if (t < off) red[t] = fmaxf(red[t], red[t+off]);
            __syncthreads();
        }
        if (t == 0) atomicMaxF(&g_Rmax, red[0]);
    } else {
        int bp = blockIdx.x - NRAY;
        for (int i = t; i < 2*HW; i += 256) sbuf[i] = g_pano[bp*2*HW + i];
        if (t < 18) sw1[t] = w1[4*9  + t];
        if (t < 50) sw2[t] = w2[4*25 + t];
        __syncthreads();
        float a1 = 0.f, a2 = 0.f;
        #pragma unroll
        for (int m = 0; m < 2; m++) {
            const float* pc = sbuf + m*HW;
            #pragma unroll
            for (int ky = 0; ky < 3; ky++) {
                int yy = ((y + ky + 7) & 7) * 32;
                #pragma unroll
                for (int kx = 0; kx < 3; kx++)
                    a1 = fmaf(sw1[m*9 + ky*3 + kx], pc[yy + ((x + kx + 31) & 31)], a1);
            }
            #pragma unroll
            for (int ky = 0; ky < 5; ky++) {
                int yy = ((y + ky + 6) & 7) * 32;
                #pragma unroll
                for (int kx = 0; kx < 5; kx++)
                    a2 = fmaf(sw2[m*25 + ky*5 + kx], pc[yy + ((x + kx + 30) & 31)], a2);
            }
        }
        float P = fw[0]*a1 + fw[1]*a2;
        g_P[bp*HW + t] = P;
        red[t] = P; __syncthreads();
        for (int off = 128; off > 0; off >>= 1) {
            if (t < off) red[t] = fmaxf(red[t], red[t+off]);
            __syncthreads();
        }
        if (t == 0) atomicMaxF(&g_Pmax, red[0]);
    }
}

// ---------------- exp of shifted tables (float4) ---------------------------
#define NR4 (NRAY*HW/4)
#define NP4 (BB*NNB*HW/4)
__global__ void k_exp() {
    int i = blockIdx.x * blockDim.x + threadIdx.x;
    if (i < NR4) {
        float rm = g_Rmax;
        float4 v = ((const float4*)g_R)[i];
        ((float4*)g_eR)[i] = make_float4(expf(v.x-rm), expf(v.y-rm), expf(v.z-rm), expf(v.w-rm));
    } else if (i < NR4 + NP4) {
        float pm = g_Pmax;
        int j = i - NR4;
        float4 v = ((const float4*)g_P)[j];
        ((float4*)g_eP)[j] = make_float4(expf(v.x-pm), expf(v.y-pm), expf(v.z-pm), expf(v.w-pm));
    }
}

// ---------------- T[bp,ind] = sum_hw eP*eR  (warp-per-ind) ------------------
__global__ void k_T() {
    int bp = blockIdx.x;
    int t = threadIdx.x, warp = t >> 5, lane = t & 31;
    __shared__ float sp[HW];
    if (t < HW) sp[t] = g_eP[bp*HW + t];
    __syncthreads();
    for (int ind = warp; ind < NRAY; ind += 8) {
        const float4* er = (const float4*)(g_eR + (size_t)ind*HW);
        float s = 0.f;
        #pragma unroll
        for (int q = 0; q < 2; q++) {
            int e = lane + q*32;
            float4 v = er[e];
            const float* pp = sp + e*4;
            s += v.x*pp[0] + v.y*pp[1] + v.z*pp[2] + v.w*pp[3];
        }
        #pragma unroll
        for (int off = 16; off > 0; off >>= 1)
            s += __shfl_xor_sync(0xffffffffu, s, off);
        if (lane == 0) g_T[bp*NRAY + ind] = s;
    }
}

// ---------------- geometry: ind, eD, Z per (b,s,p) --------------------------
__global__ void k_geo(const float* __restrict__ bbox, const float* __restrict__ locs) {
    int b = blockIdx.y;
    int s = blockIdx.x * 256 + threadIdx.x;
    int t = threadIdx.x;
    __shared__ float sT[NNB*NRAY];
    __shared__ float sl[NNB*2];
    __shared__ float sb[4];
    for (int i = t; i < NNB*NRAY; i += 256) sT[i] = g_T[b*NNB*NRAY + i];
    if (t < NNB*2) sl[t] = locs[b*NNB*2 + t];
    if (t < 4)     sb[t] = bbox[b*4 + t];
    __syncthreads();
    int iy = s >> 5, ix = s & 31;
    float ystep = __fdiv_rn(sb[2] - sb[0], 31.0f);
    float xstep = __fdiv_rn(sb[3] - sb[1], 31.0f);
    float py = __fadd_rn(sb[0], __fmul_rn((float)iy, ystep));
    float px = __fadd_rn(sb[1], __fmul_rn((float)ix, xstep));
    float alpha = g_alpha;
    float Z = 0.f;
    int base = (b*LL + s)*NNB;
    for (int p = 0; p < NNB; p++) {
        float dy = py - sl[2*p];
        float dx = px - sl[2*p + 1];
        float D = sqrtf(__fadd_rn(__fadd_rn(__fmul_rn(dy,dy), __fmul_rn(dx,dx)), 1e-12f));
        float th = atan2f(dx, dy);
        if (th < 0.f) th += 6.283185307179586f;
        float deg = __fmul_rn(th, 57.29577951308232f);
        int ind = (int)rintf(deg);
        if (ind >= 360) ind -= 360;
        float eD = expf(alpha * D);
        g_ind[base + p] = ind;
        g_eD[base + p]  = eD;
        Z = fmaf(eD, sT[p*NRAY + ind], Z);
    }
    g_invZ[b*LL + s] = 1.0f / Z;
}

// ---------------- G GEMM (FFMA2, double-buffered) ---------------------------
// G[bp, ind, f] = sum_hw eR[ind,hw] * feats[bp,f,hw] * eP[bp,hw]
#define TM 64
#define TN 128
#define TK 16
#define AROW (TM*2 + 4)   // duplicated A row, padded; 528B = 33*16 (keeps 16B align)
__global__ __launch_bounds__(256) void k_gemmG(const float* __restrict__ feats) {
    int m0 = blockIdx.x * TM;                  // ind tile
    int bp = blockIdx.z * NNB + blockIdx.y;    // (b,p)
    const float* fbase = feats + (size_t)bp*CC*HW;
    const float* epb   = g_eP + bp*HW;
    __shared__ __align__(16) float As2[2][TK][AROW];   // duplicated (a,a) pairs
    __shared__ __align__(16) float Bs[2][TK][TN];
    int tid = threadIdx.x;
    int tx = tid & 15;      // f group (8 wide)
    int ty = tid >> 4;      // ind group (4 wide)
    int a_mi = tid >> 2, a_kq = tid & 3;   // A fill: 64 m x 4-float k quad
    int b_fi = tid >> 1, b_kq = tid & 1;   // B fill: 128 f x 8-float k chunk

    unsigned long long acc[4][4];
    #pragma unroll
    for (int i = 0; i < 4; i++)
        #pragma unroll
        for (int j = 0; j < 4; j++) acc[i][j] = 0ull;

    // prologue: load k0=0 tile and store into buffer 0
    float4 av = make_float4(0.f,0.f,0.f,0.f);
    if (m0 + a_mi < NRAY) av = *(const float4*)(g_eR + (size_t)(m0+a_mi)*HW + a_kq*4);
    float4 fv0 = *(const float4*)(fbase + (size_t)b_fi*HW + b_kq*8);
    float4 ev0 = *(const float4*)(epb + b_kq*8);
    float4 fv1 = *(const float4*)(fbase + (size_t)b_fi*HW + b_kq*8 + 4);
    float4 ev1 = *(const float4*)(epb + b_kq*8 + 4);
    {
        *(float2*)&As2[0][a_kq*4+0][2*a_mi] = make_float2(av.x, av.x);
        *(float2*)&As2[0][a_kq*4+1][2*a_mi] = make_float2(av.y, av.y);
        *(float2*)&As2[0][a_kq*4+2][2*a_mi] = make_float2(av.z, av.z);
        *(float2*)&As2[0][a_kq*4+3][2*a_mi] = make_float2(av.w, av.w);
        int kk = b_kq*8;
        Bs[0][kk+0][b_fi] = fv0.x*ev0.x; Bs[0][kk+1][b_fi] = fv0.y*ev0.y;
        Bs[0][kk+2][b_fi] = fv0.z*ev0.z; Bs[0][kk+3][b_fi] = fv0.w*ev0.w;
        Bs[0][kk+4][b_fi] = fv1.x*ev1.x; Bs[0][kk+5][b_fi] = fv1.y*ev1.y;
        Bs[0][kk+6][b_fi] = fv1.z*ev1.z; Bs[0][kk+7][b_fi] = fv1.w*ev1.w;
    }
    __syncthreads();

    #pragma unroll
    for (int it = 0; it < HW/TK; it++) {
        int buf = it & 1;
        // prefetch next tile into the other buffer (no one reads it this iter)
        if (it < HW/TK - 1) {
            int k0 = (it+1)*TK;
            float4 pav = make_float4(0.f,0.f,0.f,0.f);
            if (m0 + a_mi < NRAY) pav = *(const float4*)(g_eR + (size_t)(m0+a_mi)*HW + k0 + a_kq*4);
            float4 pf0 = *(const float4*)(fbase + (size_t)b_fi*HW + k0 + b_kq*8);
            float4 pe0 = *(const float4*)(epb + k0 + b_kq*8);
            float4 pf1 = *(const float4*)(fbase + (size_t)b_fi*HW + k0 + b_kq*8 + 4);
            float4 pe1 = *(const float4*)(epb + k0 + b_kq*8 + 4);
            int nb = buf ^ 1;
            *(float2*)&As2[nb][a_kq*4+0][2*a_mi] = make_float2(pav.x, pav.x);
            *(float2*)&As2[nb][a_kq*4+1][2*a_mi] = make_float2(pav.y, pav.y);
            *(float2*)&As2[nb][a_kq*4+2][2*a_mi] = make_float2(pav.z, pav.z);
            *(float2*)&As2[nb][a_kq*4+3][2*a_mi] = make_float2(pav.w, pav.w);
            int kk = b_kq*8;
            Bs[nb][kk+0][b_fi] = pf0.x*pe0.x; Bs[nb][kk+1][b_fi] = pf0.y*pe0.y;
            Bs[nb][kk+2][b_fi] = pf0.z*pe0.z; Bs[nb][kk+3][b_fi] = pf0.w*pe0.w;
            Bs[nb][kk+4][b_fi] = pf1.x*pe1.x; Bs[nb][kk+5][b_fi] = pf1.y*pe1.y;
            Bs[nb][kk+6][b_fi] = pf1.z*pe1.z; Bs[nb][kk+7][b_fi] = pf1.w*pe1.w;
        }
        #pragma unroll
        for (int kk = 0; kk < TK; kk++) {
            const ulonglong2* ap = (const ulonglong2*)&As2[buf][kk][ty*8];
            ulonglong2 aA = ap[0], aB = ap[1];
            const ulonglong2* bpt = (const ulonglong2*)&Bs[buf][kk][tx*8];
            ulonglong2 bA = bpt[0], bB = bpt[1];
            FMA_F32X2(acc[0][0], aA.x, bA.x, acc[0][0]);
            FMA_F32X2(acc[0][1], aA.x, bA.y, acc[0][1]);
            FMA_F32X2(acc[0][2], aA.x, bB.x, acc[0][2]);
            FMA_F32X2(acc[0][3], aA.x, bB.y, acc[0][3]);
            FMA_F32X2(acc[1][0], aA.y, bA.x, acc[1][0]);
            FMA_F32X2(acc[1][1], aA.y, bA.y, acc[1][1]);
            FMA_F32X2(acc[1][2], aA.y, bB.x, acc[1][2]);
            FMA_F32X2(acc[1][3], aA.y, bB.y, acc[1][3]);
            FMA_F32X2(acc[2][0], aB.x, bA.x, acc[2][0]);
            FMA_F32X2(acc[2][1], aB.x, bA.y, acc[2][1]);
            FMA_F32X2(acc[2][2], aB.x, bB.x, acc[2][2]);
            FMA_F32X2(acc[2][3], aB.x, bB.y, acc[2][3]);
            FMA_F32X2(acc[3][0], aB.y, bA.x, acc[3][0]);
            FMA_F32X2(acc[3][1], aB.y, bA.y, acc[3][1]);
            FMA_F32X2(acc[3][2], aB.y, bB.x, acc[3][2]);
            FMA_F32X2(acc[3][3], aB.y, bB.y, acc[3][3]);
        }
        __syncthreads();
    }

    float* gb = g_G + ((size_t)bp*NRAY + m0)*CC;
    #pragma unroll
    for (int i = 0; i < 4; i++) {
        int m = ty*4 + i;
        if (m0 + m < NRAY) {
            #pragma unroll
            for (int j = 0; j < 4; j++)
                *(float2*)&gb[(size_t)m*CC + tx*8 + j*2] = *(float2*)&acc[i][j];
        }
    }
}

// ---------------- merged outputs: grid_feats + attn ------------------------
__global__ void k_final(float* __restrict__ out) {
    int s = blockIdx.x, b = blockIdx.y, t = threadIdx.x;
    __shared__ int   si[NNB];
    __shared__ float se[NNB];
    __shared__ float sz;
    int base = (b*LL + s)*NNB;
    if (t < NNB) { si[t] = g_ind[base + t]; se[t] = g_eD[base + t]; }
    if (t == 0)  sz = g_invZ[b*LL + s];
    __syncthreads();
    float invZ = sz;
    if (t < CC) {
        float acc = 0.f;
        #pragma unroll
        for (int p = 0; p < NNB; p++)
            acc = fmaf(se[p], g_G[((size_t)(b*NNB + p)*NRAY + si[p])*CC + t], acc);
        out[(size_t)(b*LL + s)*CC + t] = acc * invZ;
    }
    float4* o = (float4*)(out + (size_t)BB*LL*CC + (size_t)base*HW);
    for (int i = t; i < NNB*(HW/4); i += 256) {
        int p = i >> 6, e = i & 63;
        float k = se[p] * invZ;
        float4 ep = ((const float4*)(g_eP + (size_t)(b*NNB + p)*HW))[e];
        float4 er = ((const float4*)(g_eR + (size_t)si[p]*HW))[e];
        o[i] = make_float4(k*ep.x*er.x, k*ep.y*er.y, k*ep.z*er.z, k*ep.w*er.w);
    }
}

// ---------------- launch -----------------------------------------------------
extern "C" void kernel_launch(void* const* d_in, const int* in_sizes, int n_in,
                              void* d_out, int out_size) {
    const float* bbox  = (const float*)d_in[0];
    const float* locs  = (const float*)d_in[1];
    const float* feats = (const float*)d_in[2];
    // d_in[3] = overhead_feat: cancels in the softmax -> unused
    const float* rays  = (const float*)d_in[4];
    const float* w1    = (const float*)d_in[5];
    const float* w2    = (const float*)d_in[7];
    const float* fw    = (const float*)d_in[9];
    float* out = (float*)d_out;

    k_pano<<<BB*NNB, 256>>>(feats, w1, w2, fw);
    k_RP<<<NRAY + BB*NNB, 256>>>(rays, w1, w2, fw);
    k_exp<<<(NR4 + NP4 + 255)/256, 256>>>();
    k_T<<<BB*NNB, 256>>>();
    dim3 gg2(4, BB);
    k_geo<<<gg2, 256>>>(bbox, locs);
    dim3 gg(6, NNB, BB);
    k_gemmG<<<gg, 256>>>(feats);
    dim3 go(LL, BB);
    k_final<<<go, 256>>>(out);
}

// round 4
// speedup vs baseline: 1.3229x; 1.0111x over previous
#include <cuda_runtime.h>
#include <math.h>

#define GSZ 32
#define LL  1024
#define BB  4
#define NNB 20
#define BP  (BB*NNB)     // 80
#define CC  128
#define HH  8
#define WW  32
#define HW  256
#define NRAY 360
#define NI   384         // padded ind count (12 tiles of 32)

// packed f32x2 FMA (Blackwell): one inst = 2 fp32 FMAs
#define FMA_F32X2(d,a,b,c) asm("fma.rn.f32x2 %0, %1, %2, %3;" : "=l"(d) : "l"(a), "l"(b), "l"(c))

// ---------------- scratch (device globals; no allocations) ----------------
__device__ float g_eR [NRAY*HW];
__device__ float g_eRT[HW*NI];          // [hw][ind], cols 360..383 garbage (never read)
__device__ float g_eP [BP*HW];
__device__ float g_ePT[HW*BP];          // [hw][bp]
__device__ float g_T  [NI*BP];          // [ind][bp], rows >=360 garbage (never read)
__device__ float g_G[(size_t)BP*NRAY*CC];   // 14.7 MB
__device__ int   g_ind[BB*LL*NNB];
__device__ float g_eD [BB*LL*NNB];
__device__ float g_invZ[BB*LL];

// ---------------- merged R/P tables: circular convs + fused exp ------------
// ray branch (blocks 0..359):   eR[ind,hw] = exp(conv(rays[ind]))
// pano branch (blocks 360..439): eP[bp,hw] = exp(conv(pano(feats[bp])))
__global__ void k_RP(const float* __restrict__ rays, const float* __restrict__ feats,
                     const float* __restrict__ w1, const float* __restrict__ w2,
                     const float* __restrict__ fw) {
    __shared__ float sbuf[3*HW];
    __shared__ float sw1[27], sw2[75];
    int t = threadIdx.x;
    int y = t >> 5, x = t & 31;

    if (blockIdx.x < NRAY) {
        int ind = blockIdx.x;
        for (int i = t; i < 3*HW; i += 256) sbuf[i] = rays[(size_t)ind*3*HW + i];
        if (t < 27) sw1[t] = w1[9  + t];   // conv1 channels 1..3
        if (t < 75) sw2[t] = w2[25 + t];   // conv2 channels 1..3
        __syncthreads();
        float a1 = 0.f, a2 = 0.f;
        #pragma unroll
        for (int c = 0; c < 3; c++) {
            const float* rc = sbuf + c*HW;
            #pragma unroll
            for (int ky = 0; ky < 3; ky++) {
                int yy = ((y + ky + 7) & 7) * 32;
                #pragma unroll
                for (int kx = 0; kx < 3; kx++)
                    a1 = fmaf(sw1[c*9 + ky*3 + kx], rc[yy + ((x + kx + 31) & 31)], a1);
            }
            #pragma unroll
            for (int ky = 0; ky < 5; ky++) {
                int yy = ((y + ky + 6) & 7) * 32;
                #pragma unroll
                for (int kx = 0; kx < 5; kx++)
                    a2 = fmaf(sw2[c*25 + ky*5 + kx], rc[yy + ((x + kx + 30) & 31)], a2);
            }
        }
        float e = expf(fw[0]*a1 + fw[1]*a2);
        g_eR [ind*HW + t]  = e;
        g_eRT[t*NI + ind]  = e;
    } else {
        int bp = blockIdx.x - NRAY;
        // pano: per-hw max/mean over C (reads feats directly)
        {
            const float* base = feats + (size_t)bp*CC*HW + t;
            float mx = -3.4e38f, sm = 0.f;
            #pragma unroll 8
            for (int c = 0; c < CC; c++) {
                float v = base[(size_t)c*HW];
                mx = fmaxf(mx, v);
                sm += v;
            }
            sbuf[t]      = mx;
            sbuf[HW + t] = sm * (1.0f/128.0f);
        }
        if (t < 18) sw1[t] = w1[4*9  + t];  // conv1 channels 4..5
        if (t < 50) sw2[t] = w2[4*25 + t];  // conv2 channels 4..5
        __syncthreads();
        float a1 = 0.f, a2 = 0.f;
        #pragma unroll
        for (int m = 0; m < 2; m++) {
            const float* pc = sbuf + m*HW;
            #pragma unroll
            for (int ky = 0; ky < 3; ky++) {
                int yy = ((y + ky + 7) & 7) * 32;
                #pragma unroll
                for (int kx = 0; kx < 3; kx++)
                    a1 = fmaf(sw1[m*9 + ky*3 + kx], pc[yy + ((x + kx + 31) & 31)], a1);
            }
            #pragma unroll
            for (int ky = 0; ky < 5; ky++) {
                int yy = ((y + ky + 6) & 7) * 32;
                #pragma unroll
                for (int kx = 0; kx < 5; kx++)
                    a2 = fmaf(sw2[m*25 + ky*5 + kx], pc[yy + ((x + kx + 30) & 31)], a2);
            }
        }
        float e = expf(fw[0]*a1 + fw[1]*a2);
        g_eP [bp*HW + t]  = e;
        g_ePT[t*BP + bp]  = e;
    }
}

// ---------------- T GEMM: T[ind,bp] = sum_hw eR[ind,hw]*eP[bp,hw] ----------
#define TTK 32
__global__ __launch_bounds__(256) void k_T() {
    __shared__ float sR[TTK][32];
    __shared__ float sP[TTK][BP];
    int ind0 = blockIdx.x * 32;
    int tid = threadIdx.x;
    int ti = tid & 31, gq = tid >> 5;       // 32 inds x 8 bp-groups of 10
    float acc[10];
    #pragma unroll
    for (int j = 0; j < 10; j++) acc[j] = 0.f;

    for (int k0 = 0; k0 < HW; k0 += TTK) {
        {   // sR: 32x32 floats = 256 float4
            int kk = tid >> 3, q = tid & 7;
            *(float4*)&sR[kk][q*4] = *(const float4*)&g_eRT[(size_t)(k0+kk)*NI + ind0 + q*4];
        }
        // sP: 32x80 floats = 640 float4
        for (int i = tid; i < TTK*(BP/4); i += 256) {
            int kk = i / (BP/4), q = i % (BP/4);
            *(float4*)&sP[kk][q*4] = *(const float4*)&g_ePT[(size_t)(k0+kk)*BP + q*4];
        }
        __syncthreads();
        #pragma unroll
        for (int kk = 0; kk < TTK; kk++) {
            float a = sR[kk][ti];
            #pragma unroll
            for (int j = 0; j < 10; j++)
                acc[j] = fmaf(a, sP[kk][gq*10 + j], acc[j]);
        }
        __syncthreads();
    }
    #pragma unroll
    for (int j = 0; j < 10; j++)
        g_T[(ind0 + ti)*BP + gq*10 + j] = acc[j];
}

// ---------------- geometry: ind, eD, Z per (b,s,p) --------------------------
__global__ void k_geo(const float* __restrict__ bbox, const float* __restrict__ locs,
                      const float* __restrict__ w1, const float* __restrict__ w2,
                      const float* __restrict__ fw) {
    int b = blockIdx.y;
    int s = blockIdx.x * 256 + threadIdx.x;
    int t = threadIdx.x;
    __shared__ float sT[NRAY*NNB];   // [ind][p]
    __shared__ float sl[NNB*2];
    __shared__ float sb[4];
    __shared__ float salpha;
    for (int i = t; i < NRAY*NNB; i += 256) {
        int ind = i / NNB, p = i % NNB;
        sT[i] = g_T[ind*BP + b*NNB + p];
    }
    if (t < NNB*2) sl[t] = locs[b*NNB*2 + t];
    if (t < 4)     sb[t] = bbox[b*4 + t];
    if (t == 0) {
        float s1 = 0.f, s2 = 0.f;
        for (int i = 0; i < 9; i++)  s1 += w1[i];
        for (int i = 0; i < 25; i++) s2 += w2[i];
        salpha = fw[0]*s1 + fw[1]*s2;
    }
    __syncthreads();
    int iy = s >> 5, ix = s & 31;
    float ystep = __fdiv_rn(sb[2] - sb[0], 31.0f);
    float xstep = __fdiv_rn(sb[3] - sb[1], 31.0f);
    float py = __fadd_rn(sb[0], __fmul_rn((float)iy, ystep));
    float px = __fadd_rn(sb[1], __fmul_rn((float)ix, xstep));
    float alpha = salpha;
    float Z = 0.f;
    int base = (b*LL + s)*NNB;
    for (int p = 0; p < NNB; p++) {
        float dy = py - sl[2*p];
        float dx = px - sl[2*p + 1];
        float D = sqrtf(__fadd_rn(__fadd_rn(__fmul_rn(dy,dy), __fmul_rn(dx,dx)), 1e-12f));
        float th = atan2f(dx, dy);
        if (th < 0.f) th += 6.283185307179586f;
        float deg = __fmul_rn(th, 57.29577951308232f);
        int ind = (int)rintf(deg);
        if (ind >= 360) ind -= 360;
        float eD = expf(alpha * D);
        g_ind[base + p] = ind;
        g_eD[base + p]  = eD;
        Z = fmaf(eD, sT[ind*NNB + p], Z);
    }
    g_invZ[b*LL + s] = 1.0f / Z;
}

// ---------------- G GEMM (FFMA2, double-buffered) ---------------------------
// G[bp, ind, f] = sum_hw eR[ind,hw] * feats[bp,f,hw] * eP[bp,hw]
#define TM 64
#define TN 128
#define TK 16
#define AROW (TM*2 + 4)
__global__ __launch_bounds__(256) void k_gemmG(const float* __restrict__ feats) {
    int m0 = blockIdx.x * TM;                  // ind tile
    int bp = blockIdx.z * NNB + blockIdx.y;    // (b,p)
    const float* fbase = feats + (size_t)bp*CC*HW;
    const float* epb   = g_eP + bp*HW;
    __shared__ __align__(16) float As2[2][TK][AROW];   // duplicated (a,a) pairs
    __shared__ __align__(16) float Bs[2][TK][TN];
    int tid = threadIdx.x;
    int tx = tid & 15;
    int ty = tid >> 4;
    int a_mi = tid >> 2, a_kq = tid & 3;
    int b_fi = tid >> 1, b_kq = tid & 1;

    unsigned long long acc[4][4];
    #pragma unroll
    for (int i = 0; i < 4; i++)
        #pragma unroll
        for (int j = 0; j < 4; j++) acc[i][j] = 0ull;

    float4 av = make_float4(0.f,0.f,0.f,0.f);
    if (m0 + a_mi < NRAY) av = *(const float4*)(g_eR + (size_t)(m0+a_mi)*HW + a_kq*4);
    float4 fv0 = *(const float4*)(fbase + (size_t)b_fi*HW + b_kq*8);
    float4 ev0 = *(const float4*)(epb + b_kq*8);
    float4 fv1 = *(const float4*)(fbase + (size_t)b_fi*HW + b_kq*8 + 4);
    float4 ev1 = *(const float4*)(epb + b_kq*8 + 4);
    {
        *(float2*)&As2[0][a_kq*4+0][2*a_mi] = make_float2(av.x, av.x);
        *(float2*)&As2[0][a_kq*4+1][2*a_mi] = make_float2(av.y, av.y);
        *(float2*)&As2[0][a_kq*4+2][2*a_mi] = make_float2(av.z, av.z);
        *(float2*)&As2[0][a_kq*4+3][2*a_mi] = make_float2(av.w, av.w);
        int kk = b_kq*8;
        Bs[0][kk+0][b_fi] = fv0.x*ev0.x; Bs[0][kk+1][b_fi] = fv0.y*ev0.y;
        Bs[0][kk+2][b_fi] = fv0.z*ev0.z; Bs[0][kk+3][b_fi] = fv0.w*ev0.w;
        Bs[0][kk+4][b_fi] = fv1.x*ev1.x; Bs[0][kk+5][b_fi] = fv1.y*ev1.y;
        Bs[0][kk+6][b_fi] = fv1.z*ev1.z; Bs[0][kk+7][b_fi] = fv1.w*ev1.w;
    }
    __syncthreads();

    #pragma unroll
    for (int it = 0; it < HW/TK; it++) {
        int buf = it & 1;
        if (it < HW/TK - 1) {
            int k0 = (it+1)*TK;
            float4 pav = make_float4(0.f,0.f,0.f,0.f);
            if (m0 + a_mi < NRAY) pav = *(const float4*)(g_eR + (size_t)(m0+a_mi)*HW + k0 + a_kq*4);
            float4 pf0 = *(const float4*)(fbase + (size_t)b_fi*HW + k0 + b_kq*8);
            float4 pe0 = *(const float4*)(epb + k0 + b_kq*8);
            float4 pf1 = *(const float4*)(fbase + (size_t)b_fi*HW + k0 + b_kq*8 + 4);
            float4 pe1 = *(const float4*)(epb + k0 + b_kq*8 + 4);
            int nb = buf ^ 1;
            *(float2*)&As2[nb][a_kq*4+0][2*a_mi] = make_float2(pav.x, pav.x);
            *(float2*)&As2[nb][a_kq*4+1][2*a_mi] = make_float2(pav.y, pav.y);
            *(float2*)&As2[nb][a_kq*4+2][2*a_mi] = make_float2(pav.z, pav.z);
            *(float2*)&As2[nb][a_kq*4+3][2*a_mi] = make_float2(pav.w, pav.w);
            int kk = b_kq*8;
            Bs[nb][kk+0][b_fi] = pf0.x*pe0.x; Bs[nb][kk+1][b_fi] = pf0.y*pe0.y;
            Bs[nb][kk+2][b_fi] = pf0.z*pe0.z; Bs[nb][kk+3][b_fi] = pf0.w*pe0.w;
            Bs[nb][kk+4][b_fi] = pf1.x*pe1.x; Bs[nb][kk+5][b_fi] = pf1.y*pe1.y;
            Bs[nb][kk+6][b_fi] = pf1.z*pe1.z; Bs[nb][kk+7][b_fi] = pf1.w*pe1.w;
        }
        #pragma unroll
        for (int kk = 0; kk < TK; kk++) {
            const ulonglong2* ap = (const ulonglong2*)&As2[buf][kk][ty*8];
            ulonglong2 aA = ap[0], aB = ap[1];
            const ulonglong2* bpt = (const ulonglong2*)&Bs[buf][kk][tx*8];
            ulonglong2 bA = bpt[0], bB = bpt[1];
            FMA_F32X2(acc[0][0], aA.x, bA.x, acc[0][0]);
            FMA_F32X2(acc[0][1], aA.x, bA.y, acc[0][1]);
            FMA_F32X2(acc[0][2], aA.x, bB.x, acc[0][2]);
            FMA_F32X2(acc[0][3], aA.x, bB.y, acc[0][3]);
            FMA_F32X2(acc[1][0], aA.y, bA.x, acc[1][0]);
            FMA_F32X2(acc[1][1], aA.y, bA.y, acc[1][1]);
            FMA_F32X2(acc[1][2], aA.y, bB.x, acc[1][2]);
            FMA_F32X2(acc[1][3], aA.y, bB.y, acc[1][3]);
            FMA_F32X2(acc[2][0], aB.x, bA.x, acc[2][0]);
            FMA_F32X2(acc[2][1], aB.x, bA.y, acc[2][1]);
            FMA_F32X2(acc[2][2], aB.x, bB.x, acc[2][2]);
            FMA_F32X2(acc[2][3], aB.x, bB.y, acc[2][3]);
            FMA_F32X2(acc[3][0], aB.y, bA.x, acc[3][0]);
            FMA_F32X2(acc[3][1], aB.y, bA.y, acc[3][1]);
            FMA_F32X2(acc[3][2], aB.y, bB.x, acc[3][2]);
            FMA_F32X2(acc[3][3], aB.y, bB.y, acc[3][3]);
        }
        __syncthreads();
    }

    float* gb = g_G + ((size_t)bp*NRAY + m0)*CC;
    #pragma unroll
    for (int i = 0; i < 4; i++) {
        int m = ty*4 + i;
        if (m0 + m < NRAY) {
            #pragma unroll
            for (int j = 0; j < 4; j++)
                *(float2*)&gb[(size_t)m*CC + tx*8 + j*2] = *(float2*)&acc[i][j];
        }
    }
}

// ---------------- merged outputs: grid_feats + attn ------------------------
__global__ void k_final(float* __restrict__ out) {
    int s = blockIdx.x, b = blockIdx.y, t = threadIdx.x;
    __shared__ int   si[NNB];
    __shared__ float se[NNB];
    __shared__ float sz;
    int base = (b*LL + s)*NNB;
    if (t < NNB) { si[t] = g_ind[base + t]; se[t] = g_eD[base + t]; }
    if (t == 0)  sz = g_invZ[b*LL + s];
    __syncthreads();
    float invZ = sz;
    if (t < CC) {
        float acc = 0.f;
        #pragma unroll
        for (int p = 0; p < NNB; p++)
            acc = fmaf(se[p], g_G[((size_t)(b*NNB + p)*NRAY + si[p])*CC + t], acc);
        out[(size_t)(b*LL + s)*CC + t] = acc * invZ;
    }
    float4* o = (float4*)(out + (size_t)BB*LL*CC + (size_t)base*HW);
    for (int i = t; i < NNB*(HW/4); i += 256) {
        int p = i >> 6, e = i & 63;
        float k = se[p] * invZ;
        float4 ep = ((const float4*)(g_eP + (size_t)(b*NNB + p)*HW))[e];
        float4 er = ((const float4*)(g_eR + (size_t)si[p]*HW))[e];
        o[i] = make_float4(k*ep.x*er.x, k*ep.y*er.y, k*ep.z*er.z, k*ep.w*er.w);
    }
}

// ---------------- launch -----------------------------------------------------
extern "C" void kernel_launch(void* const* d_in, const int* in_sizes, int n_in,
                              void* d_out, int out_size) {
    const float* bbox  = (const float*)d_in[0];
    const float* locs  = (const float*)d_in[1];
    const float* feats = (const float*)d_in[2];
    // d_in[3] = overhead_feat: cancels in the softmax -> unused
    const float* rays  = (const float*)d_in[4];
    const float* w1    = (const float*)d_in[5];
    const float* w2    = (const float*)d_in[7];
    const float* fw    = (const float*)d_in[9];
    float* out = (float*)d_out;

    k_RP<<<NRAY + BP, 256>>>(rays, feats, w1, w2, fw);
    k_T<<<NI/32, 256>>>();
    dim3 gg2(4, BB);
    k_geo<<<gg2, 256>>>(bbox, locs, w1, w2, fw);
    dim3 gg(6, NNB, BB);
    k_gemmG<<<gg, 256>>>(feats);
    dim3 go(LL, BB);
    k_final<<<go, 256>>>(out);
}